// round 12
// baseline (speedup 1.0000x reference)
#include <cuda_runtime.h>

// Problem constants (from reference_code)
#define Bn      64
#define h_img   416
#define w_img   416
#define H_out   608
#define W_out   608
#define ROW_OFF 85
#define COL_OFF 80

#define W4     (W_out / 4)    // 152 float4 per output row
#define w4_    (w_img / 4)    // 104 float4 per img row
#define X4_OFF (COL_OFF / 4)  // 20  (aligned: COL_OFF % 4 == 0)

// W4 * H_out = 152 * 608 = 92416 = 361 * 256  -> exact grid, no bounds check
//
// Converged configuration. DRAM-bound at the B300 mixed-stream ceiling:
// 421 MB minimum traffic at ~6.84 TB/s effective (~85% of 8 TB/s spec).
// Tested and flat/worse: occupancy 28-84%, unroll x2/x4, persistent 1-wave,
// L2 partitioning, store policy, split-by-traffic-type kernels.

__global__ void __launch_bounds__(256, 8)
composite_kernel(const float4* __restrict__ img,   // [B,3,h,w] as float4
                 const float4* __restrict__ ref,   // [1,3,H,W] as float4
                 float4* __restrict__ out)         // [B,3,H,W] as float4
{
    const int idx = blockIdx.x * 256 + threadIdx.x;   // 0 .. 92415, covers (y, x4)
    const int b   = blockIdx.y;

    const int x4 = idx % W4;
    const int y  = idx / W4;

    // Reference pixels, all 3 channels (4.4 MB tensor -> L2-resident)
    float4 o0 = ref[(size_t)(0 * H_out + y) * W4 + x4];
    float4 o1 = ref[(size_t)(1 * H_out + y) * W4 + x4];
    float4 o2 = ref[(size_t)(2 * H_out + y) * W4 + x4];

    const int ry  = y  - ROW_OFF;
    const int rx4 = x4 - X4_OFF;
    if (ry >= 0 && ry < h_img && rx4 >= 0 && rx4 < w4_) {
        const size_t ibase = (size_t)b * 3 * h_img * w4_ + (size_t)ry * w4_ + rx4;
        // channel 2 is both the mask and the channel-2 payload; stream (read-once)
        const float4 m  = __ldcs(&img[ibase + (size_t)2 * h_img * w4_]);
        const float4 i0 = __ldcs(&img[ibase]);
        const float4 i1 = __ldcs(&img[ibase + (size_t)1 * h_img * w4_]);

        if (m.x != 0.0f) { o0.x = i0.x; o1.x = i1.x; o2.x = m.x; }
        if (m.y != 0.0f) { o0.y = i0.y; o1.y = i1.y; o2.y = m.y; }
        if (m.z != 0.0f) { o0.z = i0.z; o1.z = i1.z; o2.z = m.z; }
        if (m.w != 0.0f) { o0.w = i0.w; o1.w = i1.w; o2.w = m.w; }
    }

    const size_t obase = (size_t)b * 3 * H_out * W4 + (size_t)y * W4 + x4;
    __stcs(&out[obase],                          o0);   // write-once: evict-first
    __stcs(&out[obase + (size_t)1 * H_out * W4], o1);
    __stcs(&out[obase + (size_t)2 * H_out * W4], o2);
}

extern "C" void kernel_launch(void* const* d_in, const int* in_sizes, int n_in,
                              void* d_out, int out_size)
{
    const float4* img = (const float4*)d_in[0];   // [64,3,416,416] f32
    const float4* ref = (const float4*)d_in[1];   // [1,3,608,608]  f32
    float4* out = (float4*)d_out;                 // [64,3,608,608] f32

    dim3 grid(361, Bn);   // 361*256 == 152*608 exactly; y-dim = batch
    composite_kernel<<<grid, 256>>>(img, ref, out);
}

// round 13
// speedup vs baseline: 1.0064x; 1.0064x over previous
#include <cuda_runtime.h>

// Problem constants (from reference_code)
#define Bn      64
#define h_img   416
#define w_img   416
#define H_out   608
#define W_out   608
#define ROW_OFF 85
#define COL_OFF 80

#define W4     (W_out / 4)    // 152 float4 per output row
#define w4_    (w_img / 4)    // 104 float4 per img row
#define X4_OFF (COL_OFF / 4)  // 20  (aligned: COL_OFF % 4 == 0)
#define PLANE  (H_out * W4)   // 92416 float4 per channel plane

// Total work items: 64 * 92416 = 5,914,624 = 11552 * 512 exactly -> no bounds check.
#define NTHREADS 512
#define NBLOCKS  11552

__global__ void __launch_bounds__(NTHREADS, 4)
composite_kernel(const float4* __restrict__ img,   // [B,3,h,w] as float4
                 const float4* __restrict__ ref,   // [1,3,H,W] as float4
                 float4* __restrict__ out)         // [B,3,H,W] as float4
{
    const int gid = blockIdx.x * NTHREADS + threadIdx.x;  // 0 .. 5,914,623
    const int b   = gid / PLANE;
    const int idx = gid - b * PLANE;
    const int y   = idx / W4;
    const int x4  = idx - y * W4;

    // Reference pixels, all 3 channels (4.4 MB tensor -> L2-resident)
    const size_t r = (size_t)y * W4 + x4;
    float4 o0 = ref[r];
    float4 o1 = ref[r + (size_t)PLANE];
    float4 o2 = ref[r + (size_t)2 * PLANE];

    const int ry  = y  - ROW_OFF;
    const int rx4 = x4 - X4_OFF;
    if (ry >= 0 && ry < h_img && rx4 >= 0 && rx4 < w4_) {
        const size_t ibase = (size_t)b * 3 * h_img * w4_ + (size_t)ry * w4_ + rx4;
        // channel 2 is both the mask and the channel-2 payload; stream (read-once)
        const float4 m  = __ldcs(&img[ibase + (size_t)2 * h_img * w4_]);
        const float4 i0 = __ldcs(&img[ibase]);
        const float4 i1 = __ldcs(&img[ibase + (size_t)1 * h_img * w4_]);

        if (m.x != 0.0f) { o0.x = i0.x; o1.x = i1.x; o2.x = m.x; }
        if (m.y != 0.0f) { o0.y = i0.y; o1.y = i1.y; o2.y = m.y; }
        if (m.z != 0.0f) { o0.z = i0.z; o1.z = i1.z; o2.z = m.z; }
        if (m.w != 0.0f) { o0.w = i0.w; o1.w = i1.w; o2.w = m.w; }
    }

    const size_t obase = (size_t)b * 3 * PLANE + r;
    __stcs(&out[obase],                     o0);   // write-once: evict-first
    __stcs(&out[obase + (size_t)PLANE],     o1);
    __stcs(&out[obase + (size_t)2 * PLANE], o2);
}

extern "C" void kernel_launch(void* const* d_in, const int* in_sizes, int n_in,
                              void* d_out, int out_size)
{
    const float4* img = (const float4*)d_in[0];   // [64,3,416,416] f32
    const float4* ref = (const float4*)d_in[1];   // [1,3,608,608]  f32
    float4* out = (float4*)d_out;                 // [64,3,608,608] f32

    composite_kernel<<<NBLOCKS, NTHREADS>>>(img, ref, out);
}

// round 14
// speedup vs baseline: 1.0168x; 1.0104x over previous
#include <cuda_runtime.h>

// Problem constants (from reference_code)
#define Bn      64
#define h_img   416
#define w_img   416
#define H_out   608
#define W_out   608
#define ROW_OFF 85
#define COL_OFF 80

#define W4     (W_out / 4)    // 152 float4 per output row
#define w4_    (w_img / 4)    // 104 float4 per img row
#define X4_OFF (COL_OFF / 4)  // 20  (aligned: COL_OFF % 4 == 0)
#define PLANE  (H_out * W4)   // 92416 float4 per channel plane

// Total work items: 64 * 92416 = 5,914,624 = 5776 * 1024 exactly -> no bounds check.
#define NTHREADS 1024
#define NBLOCKS  5776

__global__ void __launch_bounds__(NTHREADS, 2)
composite_kernel(const float4* __restrict__ img,   // [B,3,h,w] as float4
                 const float4* __restrict__ ref,   // [1,3,H,W] as float4
                 float4* __restrict__ out)         // [B,3,H,W] as float4
{
    const int gid = blockIdx.x * NTHREADS + threadIdx.x;  // 0 .. 5,914,623
    const int b   = gid / PLANE;
    const int idx = gid - b * PLANE;
    const int y   = idx / W4;
    const int x4  = idx - y * W4;

    // Reference pixels, all 3 channels (4.4 MB tensor -> L2-resident)
    const size_t r = (size_t)y * W4 + x4;
    float4 o0 = ref[r];
    float4 o1 = ref[r + (size_t)PLANE];
    float4 o2 = ref[r + (size_t)2 * PLANE];

    const int ry  = y  - ROW_OFF;
    const int rx4 = x4 - X4_OFF;
    if (ry >= 0 && ry < h_img && rx4 >= 0 && rx4 < w4_) {
        const size_t ibase = (size_t)b * 3 * h_img * w4_ + (size_t)ry * w4_ + rx4;
        // channel 2 is both the mask and the channel-2 payload; stream (read-once)
        const float4 m  = __ldcs(&img[ibase + (size_t)2 * h_img * w4_]);
        const float4 i0 = __ldcs(&img[ibase]);
        const float4 i1 = __ldcs(&img[ibase + (size_t)1 * h_img * w4_]);

        if (m.x != 0.0f) { o0.x = i0.x; o1.x = i1.x; o2.x = m.x; }
        if (m.y != 0.0f) { o0.y = i0.y; o1.y = i1.y; o2.y = m.y; }
        if (m.z != 0.0f) { o0.z = i0.z; o1.z = i1.z; o2.z = m.z; }
        if (m.w != 0.0f) { o0.w = i0.w; o1.w = i1.w; o2.w = m.w; }
    }

    const size_t obase = (size_t)b * 3 * PLANE + r;
    __stcs(&out[obase],                     o0);   // write-once: evict-first
    __stcs(&out[obase + (size_t)PLANE],     o1);
    __stcs(&out[obase + (size_t)2 * PLANE], o2);
}

extern "C" void kernel_launch(void* const* d_in, const int* in_sizes, int n_in,
                              void* d_out, int out_size)
{
    const float4* img = (const float4*)d_in[0];   // [64,3,416,416] f32
    const float4* ref = (const float4*)d_in[1];   // [1,3,608,608]  f32
    float4* out = (float4*)d_out;                 // [64,3,608,608] f32

    composite_kernel<<<NBLOCKS, NTHREADS>>>(img, ref, out);
}

// round 15
// speedup vs baseline: 1.0265x; 1.0095x over previous
#include <cuda_runtime.h>

// Problem constants (from reference_code)
#define Bn      64
#define h_img   416
#define w_img   416
#define H_out   608
#define W_out   608
#define ROW_OFF 85
#define COL_OFF 80

#define W4     (W_out / 4)    // 152 float4 per output row
#define w4_    (w_img / 4)    // 104 float4 per img row
#define X4_OFF (COL_OFF / 4)  // 20  (aligned: COL_OFF % 4 == 0)
#define PLANE  (H_out * W4)   // 92416 float4 per channel plane

// Total work items: 64 * 92416 = 5,914,624 = 5776 * 1024 exactly -> no bounds check.
//
// Converged configuration (best of 12 measured variants):
//   - 1 float4 position per thread, all 3 channels (mask read once)
//   - block=1024 (longest coherent store bursts per CTA; 256->512->1024
//     monotonically improved DRAM scheduling: 62.0 -> 61.1 -> 60.9 us ncu)
//   - __ldcs img (read-once), __stcs out (write-once), ref default (L2-resident)
// At ~6.9 TB/s effective on 421 MB minimum traffic (~86% of 8 TB/s spec):
// the B300 mixed-stream DRAM ceiling. Tested and flat/worse: occupancy 28-84%,
// unroll x2/x4, persistent 1-wave, L2 partitioning, store policy, kernel split.
#define NTHREADS 1024
#define NBLOCKS  5776

__global__ void __launch_bounds__(NTHREADS, 2)
composite_kernel(const float4* __restrict__ img,   // [B,3,h,w] as float4
                 const float4* __restrict__ ref,   // [1,3,H,W] as float4
                 float4* __restrict__ out)         // [B,3,H,W] as float4
{
    const int gid = blockIdx.x * NTHREADS + threadIdx.x;  // 0 .. 5,914,623
    const int b   = gid / PLANE;
    const int idx = gid - b * PLANE;
    const int y   = idx / W4;
    const int x4  = idx - y * W4;

    // Reference pixels, all 3 channels (4.4 MB tensor -> L2-resident)
    const size_t r = (size_t)y * W4 + x4;
    float4 o0 = ref[r];
    float4 o1 = ref[r + (size_t)PLANE];
    float4 o2 = ref[r + (size_t)2 * PLANE];

    const int ry  = y  - ROW_OFF;
    const int rx4 = x4 - X4_OFF;
    if (ry >= 0 && ry < h_img && rx4 >= 0 && rx4 < w4_) {
        const size_t ibase = (size_t)b * 3 * h_img * w4_ + (size_t)ry * w4_ + rx4;
        // channel 2 is both the mask and the channel-2 payload; stream (read-once)
        const float4 m  = __ldcs(&img[ibase + (size_t)2 * h_img * w4_]);
        const float4 i0 = __ldcs(&img[ibase]);
        const float4 i1 = __ldcs(&img[ibase + (size_t)1 * h_img * w4_]);

        if (m.x != 0.0f) { o0.x = i0.x; o1.x = i1.x; o2.x = m.x; }
        if (m.y != 0.0f) { o0.y = i0.y; o1.y = i1.y; o2.y = m.y; }
        if (m.z != 0.0f) { o0.z = i0.z; o1.z = i1.z; o2.z = m.z; }
        if (m.w != 0.0f) { o0.w = i0.w; o1.w = i1.w; o2.w = m.w; }
    }

    const size_t obase = (size_t)b * 3 * PLANE + r;
    __stcs(&out[obase],                     o0);   // write-once: evict-first
    __stcs(&out[obase + (size_t)PLANE],     o1);
    __stcs(&out[obase + (size_t)2 * PLANE], o2);
}

extern "C" void kernel_launch(void* const* d_in, const int* in_sizes, int n_in,
                              void* d_out, int out_size)
{
    const float4* img = (const float4*)d_in[0];   // [64,3,416,416] f32
    const float4* ref = (const float4*)d_in[1];   // [1,3,608,608]  f32
    float4* out = (float4*)d_out;                 // [64,3,608,608] f32

    composite_kernel<<<NBLOCKS, NTHREADS>>>(img, ref, out);
}